// round 1
// baseline (speedup 1.0000x reference)
#include <cuda_runtime.h>

#define TPB   256
#define UNITS 64

// ---------- packed f32x2 helpers (Blackwell sm_100+) ----------
__device__ __forceinline__ unsigned long long pack2(float lo, float hi) {
    unsigned long long r;
    asm("mov.b64 %0, {%1, %2};" : "=l"(r) : "f"(lo), "f"(hi));
    return r;
}
__device__ __forceinline__ void unpack2(unsigned long long v, float& lo, float& hi) {
    asm("mov.b64 {%0, %1}, %2;" : "=f"(lo), "=f"(hi) : "l"(v));
}
__device__ __forceinline__ unsigned long long ffma2(unsigned long long a,
                                                    unsigned long long b,
                                                    unsigned long long c) {
    unsigned long long d;
    asm("fma.rn.f32x2 %0, %1, %2, %3;" : "=l"(d) : "l"(a), "l"(b), "l"(c));
    return d;
}

// ---------- fast, overflow-safe activations (EX2/RCP on MUFU pipe) ----------
__device__ __forceinline__ float sigm(float x) {
    // 1/(1+e^-x): x->+inf => exp->0 => 1; x->-inf => exp->inf => 0. No NaN.
    return __fdividef(1.f, 1.f + __expf(-x));
}
__device__ __forceinline__ float tanh_fast(float x) {
    // 1 - 2/(e^{2x}+1): x->+inf => 1; x->-inf => -1. No NaN.
    return 1.f - 2.f * __fdividef(1.f, __expf(2.f * x) + 1.f);
}

// Apply gates for 8 units (unit block ub), update c (registers), write h to SMEM.
// acc layout: acc[g*4+p] = f32x2 pair of z for gate g, units (ub*8+2p, ub*8+2p+1)
__device__ __forceinline__ void gates_update(const unsigned long long* acc, float* c,
                                             int ub, float* Hnext, int tid) {
#pragma unroll
    for (int p = 0; p < 4; ++p) {
        float zi0, zi1, zf0, zf1, zg0, zg1, zo0, zo1;
        unpack2(acc[0 * 4 + p], zi0, zi1);
        unpack2(acc[1 * 4 + p], zf0, zf1);
        unpack2(acc[2 * 4 + p], zg0, zg1);
        unpack2(acc[3 * 4 + p], zo0, zo1);
        {
            const int u = ub * 8 + 2 * p;
            float i = sigm(zi0), f = sigm(zf0), g = tanh_fast(zg0), o = sigm(zo0);
            float cn = fmaf(f, c[u], i * g);
            c[u] = cn;
            Hnext[u * TPB + tid] = o * tanh_fast(cn);
        }
        {
            const int u = ub * 8 + 2 * p + 1;
            float i = sigm(zi1), f = sigm(zf1), g = tanh_fast(zg1), o = sigm(zo1);
            float cn = fmaf(f, c[u], i * g);
            c[u] = cn;
            Hnext[u * TPB + tid] = o * tanh_fast(cn);
        }
    }
}

// SMEM layout (floats):
//   sU  [64*256]          = 16384   (recurrent kernel, row-major [k][col])
//   sH  [2][64][TPB]      = 32768   (double-buffered h, layout [k][tid] -> conflict-free)
//   sW  [256], sB [256], sWd [64]
#define SMEM_FLOATS (16384 + 32768 + 256 + 256 + 64)

__global__ void __launch_bounds__(TPB, 1)
lstm_fused(const float* __restrict__ x, const float* __restrict__ W,
           const float* __restrict__ U, const float* __restrict__ b,
           const float* __restrict__ Wd, const float* __restrict__ bd,
           float* __restrict__ out, int Bn)
{
    extern __shared__ float sm[];
    float* sU  = sm;             // 16384
    float* sH  = sm + 16384;     // 32768
    float* sW  = sH + 32768;     // 256
    float* sB  = sW + 256;       // 256
    float* sWd = sB + 256;       // 64

    const int tid = threadIdx.x;

    // Cooperative loads of weights into SMEM (vectorized, coalesced)
    {
        const float4* src = (const float4*)U;
        float4* dst = (float4*)sU;
#pragma unroll
        for (int i = 0; i < 16; ++i) dst[tid + i * TPB] = src[tid + i * TPB];
    }
    sW[tid] = W[tid];
    sB[tid] = b[tid];
    if (tid < UNITS) sWd[tid] = Wd[tid];
    __syncthreads();

    const int row = blockIdx.x * TPB + tid;
    if (row >= Bn) return;   // no further block-wide syncs below

    float x5[5];
#pragma unroll
    for (int t = 0; t < 5; ++t) x5[t] = __ldg(&x[row * 5 + t]);

    float c[UNITS];
#pragma unroll
    for (int u = 0; u < UNITS; ++u) c[u] = 0.f;

    // ---- t = 0: h0 == 0, so z = x0*W + b (no matvec) -> writes h into buffer 0 ----
    {
        unsigned long long xt2 = pack2(x5[0], x5[0]);
#pragma unroll
        for (int ub = 0; ub < 8; ++ub) {
            unsigned long long acc[16];
#pragma unroll
            for (int g = 0; g < 4; ++g) {
                const unsigned long long* w2 = (const unsigned long long*)(sW + g * 64 + ub * 8);
                const unsigned long long* b2 = (const unsigned long long*)(sB + g * 64 + ub * 8);
#pragma unroll
                for (int p = 0; p < 4; ++p) acc[g * 4 + p] = ffma2(xt2, w2[p], b2[p]);
            }
            gates_update(acc, c, ub, sH /*buffer 0*/, tid);
        }
    }

    // ---- t = 1..4: z = xt*W + h@U + b ----
#pragma unroll 1
    for (int t = 1; t < 5; ++t) {
        const float* Hcur = sH + (((t & 1) ^ 1) << 14);  // * 16384
        float* Hnext      = sH + ((t & 1) << 14);
        unsigned long long xt2 = pack2(x5[t], x5[t]);
#pragma unroll
        for (int ub = 0; ub < 8; ++ub) {
            unsigned long long acc[16];
#pragma unroll
            for (int g = 0; g < 4; ++g) {
                const unsigned long long* w2 = (const unsigned long long*)(sW + g * 64 + ub * 8);
                const unsigned long long* b2 = (const unsigned long long*)(sB + g * 64 + ub * 8);
#pragma unroll
                for (int p = 0; p < 4; ++p) acc[g * 4 + p] = ffma2(xt2, w2[p], b2[p]);
            }
            // Recurrent matvec: 64 k-steps, 16 f32x2 FMAs each (32 FMA lanes/pair-instr)
#pragma unroll 8
            for (int k = 0; k < 64; ++k) {
                float hk = Hcur[k * TPB + tid];                 // conflict-free LDS
                unsigned long long hk2 = pack2(hk, hk);
                const float* urow = sU + k * 256 + ub * 8;      // broadcast LDS.128
#pragma unroll
                for (int g = 0; g < 4; ++g) {
                    const unsigned long long* u2 = (const unsigned long long*)(urow + g * 64);
#pragma unroll
                    for (int p = 0; p < 4; ++p)
                        acc[g * 4 + p] = ffma2(hk2, u2[p], acc[g * 4 + p]);
                }
            }
            gates_update(acc, c, ub, Hnext, tid);
        }
    }

    // ---- Dense(1, relu): final h lives in buffer 0 (t=4 wrote (4&1)=0) ----
    float accv = __ldg(&bd[0]);
#pragma unroll
    for (int u = 0; u < UNITS; ++u)
        accv = fmaf(sH[u * TPB + tid], sWd[u], accv);
    out[row] = fmaxf(accv, 0.f);
}

extern "C" void kernel_launch(void* const* d_in, const int* in_sizes, int n_in,
                              void* d_out, int out_size) {
    const float* x  = (const float*)d_in[0];
    const float* W  = (const float*)d_in[1];
    const float* U  = (const float*)d_in[2];
    const float* b  = (const float*)d_in[3];
    const float* Wd = (const float*)d_in[4];
    const float* bd = (const float*)d_in[5];
    float* out = (float*)d_out;

    const int Bn = in_sizes[0] / 5;                  // x is [B, 5, 1]
    const int smem_bytes = SMEM_FLOATS * (int)sizeof(float);   // 198912 B

    cudaFuncSetAttribute(lstm_fused, cudaFuncAttributeMaxDynamicSharedMemorySize,
                         smem_bytes);

    const int grid = (Bn + TPB - 1) / TPB;
    lstm_fused<<<grid, TPB, smem_bytes>>>(x, W, U, b, Wd, bd, out, Bn);
}

// round 2
// speedup vs baseline: 1.0032x; 1.0032x over previous
#include <cuda_runtime.h>

#define TPB   256
#define UNITS 64

typedef unsigned long long ull;

// ---------- packed f32x2 helpers (Blackwell sm_100+) ----------
__device__ __forceinline__ ull pack2(float lo, float hi) {
    ull r;
    asm("mov.b64 %0, {%1, %2};" : "=l"(r) : "f"(lo), "f"(hi));
    return r;
}
__device__ __forceinline__ void unpack2(ull v, float& lo, float& hi) {
    asm("mov.b64 {%0, %1}, %2;" : "=f"(lo), "=f"(hi) : "l"(v));
}
__device__ __forceinline__ ull ffma2(ull a, ull b, ull c) {
    ull d;
    asm("fma.rn.f32x2 %0, %1, %2, %3;" : "=l"(d) : "l"(a), "l"(b), "l"(c));
    return d;
}

// ---------- fast, overflow-safe activations (EX2/RCP on MUFU pipe) ----------
__device__ __forceinline__ float sigm(float x) {
    return __fdividef(1.f, 1.f + __expf(-x));
}
__device__ __forceinline__ float tanh_fast(float x) {
    return 1.f - 2.f * __fdividef(1.f, __expf(2.f * x) + 1.f);
}

// Apply gates for 8 units (block ub): read z from acc, update c (regs), h -> SMEM.
__device__ __forceinline__ void gates_update(const ull* acc, float* c,
                                             int ub, float* Hnext, int tid) {
#pragma unroll
    for (int p = 0; p < 4; ++p) {
        float zi0, zi1, zf0, zf1, zg0, zg1, zo0, zo1;
        unpack2(acc[0 * 4 + p], zi0, zi1);
        unpack2(acc[1 * 4 + p], zf0, zf1);
        unpack2(acc[2 * 4 + p], zg0, zg1);
        unpack2(acc[3 * 4 + p], zo0, zo1);
        {
            const int u = ub * 8 + 2 * p;
            float i = sigm(zi0), f = sigm(zf0), g = tanh_fast(zg0), o = sigm(zo0);
            float cn = fmaf(f, c[u], i * g);
            c[u] = cn;
            Hnext[u * TPB + tid] = o * tanh_fast(cn);
        }
        {
            const int u = ub * 8 + 2 * p + 1;
            float i = sigm(zi1), f = sigm(zf1), g = tanh_fast(zg1), o = sigm(zo1);
            float cn = fmaf(f, c[u], i * g);
            c[u] = cn;
            Hnext[u * TPB + tid] = o * tanh_fast(cn);
        }
    }
}

// SMEM (floats): sU 16384 | sH 2*64*TPB = 32768 | sW 256 | sB 256 | sWd 64
#define SMEM_FLOATS (16384 + 32768 + 256 + 256 + 64)

__global__ void __launch_bounds__(TPB, 1)
lstm_fused(const float* __restrict__ x, const float* __restrict__ W,
           const float* __restrict__ U, const float* __restrict__ b,
           const float* __restrict__ Wd, const float* __restrict__ bd,
           float* __restrict__ out, int Bn)
{
    extern __shared__ float sm[];
    float* sU  = sm;             // 16384
    float* sH  = sm + 16384;     // 32768 (double buffer, [k][tid] conflict-free)
    float* sW  = sH + 32768;     // 256
    float* sB  = sW + 256;       // 256
    float* sWd = sB + 256;       // 64

    const int tid = threadIdx.x;

    // Cooperative weight loads (vectorized, coalesced)
    {
        const float4* src = (const float4*)U;
        float4* dst = (float4*)sU;
#pragma unroll
        for (int i = 0; i < 16; ++i) dst[tid + i * TPB] = src[tid + i * TPB];
    }
    sW[tid] = W[tid];
    sB[tid] = b[tid];
    if (tid < UNITS) sWd[tid] = Wd[tid];
    __syncthreads();

    const int row = blockIdx.x * TPB + tid;
    if (row >= Bn) return;   // no block-wide syncs after this point

    float x5[5];
#pragma unroll
    for (int t = 0; t < 5; ++t) x5[t] = __ldg(&x[row * 5 + t]);

    float c[UNITS];
#pragma unroll
    for (int u = 0; u < UNITS; ++u) c[u] = 0.f;

    // ---- t = 0: h0 == 0 -> z = x0*W + b (no matvec); h into buffer 0 ----
    {
        ull xt2 = pack2(x5[0], x5[0]);
#pragma unroll
        for (int ub = 0; ub < 8; ++ub) {
            ull acc[16];
#pragma unroll
            for (int g = 0; g < 4; ++g) {
                const ulonglong2 wa = *(const ulonglong2*)(sW + g * 64 + ub * 8);
                const ulonglong2 wb = *(const ulonglong2*)(sW + g * 64 + ub * 8 + 4);
                const ulonglong2 ba = *(const ulonglong2*)(sB + g * 64 + ub * 8);
                const ulonglong2 bb = *(const ulonglong2*)(sB + g * 64 + ub * 8 + 4);
                acc[g * 4 + 0] = ffma2(xt2, wa.x, ba.x);
                acc[g * 4 + 1] = ffma2(xt2, wa.y, ba.y);
                acc[g * 4 + 2] = ffma2(xt2, wb.x, bb.x);
                acc[g * 4 + 3] = ffma2(xt2, wb.y, bb.y);
            }
            gates_update(acc, c, ub, sH /*buffer 0*/, tid);
        }
    }

    // ---- t = 1..4: z = xt*W + h@U + b ----
#pragma unroll 1
    for (int t = 1; t < 5; ++t) {
        const float* Hcur = sH + (((t & 1) ^ 1) << 14);  // * 16384
        float* Hnext      = sH + ((t & 1) << 14);
        ull xt2 = pack2(x5[t], x5[t]);
#pragma unroll
        for (int ub = 0; ub < 8; ++ub) {
            ull acc[16];
#pragma unroll
            for (int g = 0; g < 4; ++g) {
                const ulonglong2 wa = *(const ulonglong2*)(sW + g * 64 + ub * 8);
                const ulonglong2 wb = *(const ulonglong2*)(sW + g * 64 + ub * 8 + 4);
                const ulonglong2 ba = *(const ulonglong2*)(sB + g * 64 + ub * 8);
                const ulonglong2 bb = *(const ulonglong2*)(sB + g * 64 + ub * 8 + 4);
                acc[g * 4 + 0] = ffma2(xt2, wa.x, ba.x);
                acc[g * 4 + 1] = ffma2(xt2, wa.y, ba.y);
                acc[g * 4 + 2] = ffma2(xt2, wb.x, bb.x);
                acc[g * 4 + 3] = ffma2(xt2, wb.y, bb.y);
            }
            // Recurrent matvec: per k -> 8x LDS.128 (U) + 1x LDS.32 (h) + 16x FFMA2
#pragma unroll 8
            for (int k = 0; k < 64; ++k) {
                float hk = Hcur[k * TPB + tid];             // conflict-free LDS.32
                ull hk2 = pack2(hk, hk);
                const float* urow = sU + k * 256 + ub * 8;  // broadcast rows
#pragma unroll
                for (int g = 0; g < 4; ++g) {
                    const ulonglong2 ua = *(const ulonglong2*)(urow + g * 64);
                    const ulonglong2 ub2 = *(const ulonglong2*)(urow + g * 64 + 4);
                    acc[g * 4 + 0] = ffma2(hk2, ua.x,  acc[g * 4 + 0]);
                    acc[g * 4 + 1] = ffma2(hk2, ua.y,  acc[g * 4 + 1]);
                    acc[g * 4 + 2] = ffma2(hk2, ub2.x, acc[g * 4 + 2]);
                    acc[g * 4 + 3] = ffma2(hk2, ub2.y, acc[g * 4 + 3]);
                }
            }
            gates_update(acc, c, ub, Hnext, tid);
        }
    }

    // ---- Dense(1, relu): final h is in buffer 0 (t=4 wrote (4&1)=0) ----
    float accv = __ldg(&bd[0]);
#pragma unroll
    for (int u = 0; u < UNITS; ++u)
        accv = fmaf(sH[u * TPB + tid], sWd[u], accv);
    out[row] = fmaxf(accv, 0.f);
}

extern "C" void kernel_launch(void* const* d_in, const int* in_sizes, int n_in,
                              void* d_out, int out_size) {
    const float* x  = (const float*)d_in[0];
    const float* W  = (const float*)d_in[1];
    const float* U  = (const float*)d_in[2];
    const float* b  = (const float*)d_in[3];
    const float* Wd = (const float*)d_in[4];
    const float* bd = (const float*)d_in[5];
    float* out = (float*)d_out;

    const int Bn = in_sizes[0] / 5;                              // x is [B, 5, 1]
    const int smem_bytes = SMEM_FLOATS * (int)sizeof(float);     // 198912 B

    cudaFuncSetAttribute(lstm_fused, cudaFuncAttributeMaxDynamicSharedMemorySize,
                         smem_bytes);

    const int grid = (Bn + TPB - 1) / TPB;
    lstm_fused<<<grid, TPB, smem_bytes>>>(x, W, U, b, Wd, bd, out, Bn);
}

// round 5
// speedup vs baseline: 2.3080x; 2.3006x over previous
#include <cuda_runtime.h>

#define TPB   256
#define ROWS  128        // batch rows per CTA
#define RPT   16         // rows per thread
#define HSTR  130        // floats per unit-row of H: 128 rows + 2 pad (even -> float2 aligned)

typedef unsigned int u32;
typedef unsigned long long ull;

// ---------- packed f32x2 helpers ----------
__device__ __forceinline__ ull pack2(float lo, float hi) {
    ull r; asm("mov.b64 %0, {%1, %2};" : "=l"(r) : "f"(lo), "f"(hi)); return r;
}
__device__ __forceinline__ void unpack2(ull v, float& lo, float& hi) {
    asm("mov.b64 {%0, %1}, %2;" : "=f"(lo), "=f"(hi) : "l"(v));
}
__device__ __forceinline__ ull ffma2(ull a, ull b, ull c) {
    ull d; asm("fma.rn.f32x2 %0, %1, %2, %3;" : "=l"(d) : "l"(a), "l"(b), "l"(c)); return d;
}

// ---------- fast, overflow-safe activations (MUFU pipe) ----------
__device__ __forceinline__ float sigm(float x)      { return __fdividef(1.f, 1.f + __expf(-x)); }
__device__ __forceinline__ float tanh_fast(float x) { return 1.f - 2.f * __fdividef(1.f, __expf(2.f * x) + 1.f); }

// SMEM layout (floats):
//   sU [64][256] = 16384 | sH [2][64*HSTR] = 2*8320 | sW[256] sB[256] sWd[64] sX[640]
#define OFF_U   0
#define OFF_H0  16384
#define OFF_H1  (OFF_H0 + 64*HSTR)
#define OFF_W   (OFF_H0 + 2*64*HSTR)
#define OFF_B   (OFF_W + 256)
#define OFF_WD  (OFF_B + 256)
#define OFF_X   (OFF_WD + 64)
#define SMEM_FLOATS (OFF_X + ROWS*5)

__global__ void __launch_bounds__(TPB, 1)
lstm_gemm(const float* __restrict__ x, const float* __restrict__ W,
          const float* __restrict__ U, const float* __restrict__ b,
          const float* __restrict__ Wd, const float* __restrict__ bd,
          float* __restrict__ out, int Bn)
{
    extern __shared__ float sm[];
    float* sU  = sm + OFF_U;
    float* sW  = sm + OFF_W;
    float* sB  = sm + OFF_B;
    float* sWd = sm + OFF_WD;
    float* sX  = sm + OFF_X;

    const int tid = threadIdx.x;
    const int cx  = tid & 31;       // column-thread: owns units {cx, cx+32}
    const int ry  = tid >> 5;       // row-thread: owns rows [ry*16, ry*16+16)
    const int r0  = ry * RPT;
    const long rowBase = (long)blockIdx.x * ROWS;

    // ---- stage weights + this CTA's x slice ----
    {
        const float4* Us = (const float4*)U;
        float4* Ud = (float4*)sU;
#pragma unroll
        for (int i = 0; i < 16; ++i) Ud[tid + i * TPB] = Us[tid + i * TPB];
        sW[tid] = W[tid];
        sB[tid] = b[tid];
        if (tid < 64) sWd[tid] = Wd[tid];
        const float* xs = x + rowBase * 5;
        for (int i = tid; i < ROWS * 5; i += TPB)
            if (rowBase * 5 + i < (long)Bn * 5) sX[i] = xs[i];
    }
    __syncthreads();

    const int u0 = cx, u1 = cx + 32;
    const float wd0 = sWd[u0], wd1 = sWd[u1];

    float c[RPT * 2];               // c-state: [row][unit]
#pragma unroll
    for (int i = 0; i < RPT * 2; ++i) c[i] = 0.f;

    float part[RPT];                // dense partials (t==4 only)

#pragma unroll 1
    for (int t = 0; t < 5; ++t) {
        ull acc[64];                // z tile: 8 row-pairs x 8 cols (4 gates x 2 units)
#pragma unroll
        for (int i = 0; i < 64; ++i) acc[i] = 0ull;

        if (t > 0) {
            const float* Hc = sm + (((t - 1) & 1) ? OFF_H1 : OFF_H0);
            const float* Ap = Hc + r0;          // H[k][row], this thread's 16 rows
            const float* Bp = sU + cx;
#pragma unroll 4
            for (int k = 0; k < 64; ++k) {
                ull av[8];                       // 8 row-pairs of h (warp-uniform broadcast)
#pragma unroll
                for (int j = 0; j < 8; ++j) {
                    float2 a2 = *(const float2*)(Ap + k * HSTR + 2 * j);
                    av[j] = pack2(a2.x, a2.y);
                }
                ull bv[8];                       // 8 cols of U, duplicated (stride-1 LDS)
#pragma unroll
                for (int g = 0; g < 4; ++g) {
                    const float b0 = Bp[k * 256 + g * 64];
                    const float b1 = Bp[k * 256 + g * 64 + 32];
                    bv[g * 2 + 0] = pack2(b0, b0);
                    bv[g * 2 + 1] = pack2(b1, b1);
                }
#pragma unroll
                for (int rp = 0; rp < 8; ++rp)
#pragma unroll
                    for (int cs = 0; cs < 8; ++cs)
                        acc[rp * 8 + cs] = ffma2(av[rp], bv[cs], acc[rp * 8 + cs]);
            }
        }

        // ---- epilogue: z = acc + x*W + b, gates, c/h update ----
        float* Hn = sm + ((t & 1) ? OFF_H1 : OFF_H0);
        float wv[8], bvv[8];
#pragma unroll
        for (int g = 0; g < 4; ++g) {
            wv[g * 2]     = sW[g * 64 + u0];  wv[g * 2 + 1]  = sW[g * 64 + u1];
            bvv[g * 2]    = sB[g * 64 + u0];  bvv[g * 2 + 1] = sB[g * 64 + u1];
        }
        const bool last = (t == 4);

#pragma unroll
        for (int rp = 0; rp < 8; ++rp) {
            float z0[8], z1[8];
#pragma unroll
            for (int cs = 0; cs < 8; ++cs) unpack2(acc[rp * 8 + cs], z0[cs], z1[cs]);
#pragma unroll
            for (int h2 = 0; h2 < 2; ++h2) {
                const int r = 2 * rp + h2;
                const float xr = sX[(r0 + r) * 5 + t];
                const float* zz = h2 ? z1 : z0;
#pragma unroll
                for (int uh = 0; uh < 2; ++uh) {
                    const float zi = zz[0 + uh] + fmaf(xr, wv[0 + uh], bvv[0 + uh]);
                    const float zf = zz[2 + uh] + fmaf(xr, wv[2 + uh], bvv[2 + uh]);
                    const float zg = zz[4 + uh] + fmaf(xr, wv[4 + uh], bvv[4 + uh]);
                    const float zo = zz[6 + uh] + fmaf(xr, wv[6 + uh], bvv[6 + uh]);
                    const float ig = sigm(zi), fg = sigm(zf);
                    const float gg = tanh_fast(zg), og = sigm(zo);
                    const float cn = fmaf(fg, c[r * 2 + uh], ig * gg);
                    c[r * 2 + uh] = cn;
                    const float h = og * tanh_fast(cn);
                    if (!last) {
                        Hn[(cx + uh * 32) * HSTR + r0 + r] = h;   // 2-way STS max
                    } else {
                        if (uh == 0) part[r] = h * wd0;
                        else         part[r] = fmaf(h, wd1, part[r]);
                    }
                }
            }
        }

        if (!last) {
            __syncthreads();        // h visible to all warps before next GEMM
        } else {
            // Dense(1, relu): reduce over units = over the 32 cx lanes of this warp
#pragma unroll
            for (int r = 0; r < RPT; ++r) {
#pragma unroll
                for (int s = 16; s; s >>= 1)
                    part[r] += __shfl_xor_sync(0xFFFFFFFFu, part[r], s);
            }
            if (cx == 0) {
                const float bdv = __ldg(bd);
#pragma unroll
                for (int r = 0; r < RPT; ++r) {
                    const long orow = rowBase + r0 + r;
                    if (orow < Bn) out[orow] = fmaxf(part[r] + bdv, 0.f);
                }
            }
        }
    }
}

extern "C" void kernel_launch(void* const* d_in, const int* in_sizes, int n_in,
                              void* d_out, int out_size) {
    const float* x  = (const float*)d_in[0];
    const float* W  = (const float*)d_in[1];
    const float* U  = (const float*)d_in[2];
    const float* b  = (const float*)d_in[3];
    const float* Wd = (const float*)d_in[4];
    const float* bd = (const float*)d_in[5];
    float* out = (float*)d_out;

    const int Bn = in_sizes[0] / 5;                           // x is [B, 5, 1]
    const int smem_bytes = SMEM_FLOATS * (int)sizeof(float);  // 136960 B

    cudaFuncSetAttribute(lstm_gemm, cudaFuncAttributeMaxDynamicSharedMemorySize,
                         smem_bytes);

    const int grid = (Bn + ROWS - 1) / ROWS;
    lstm_gemm<<<grid, TPB, smem_bytes>>>(x, W, U, b, Wd, bd, out, Bn);
}

// round 6
// speedup vs baseline: 2.8024x; 1.2142x over previous
#include <cuda_runtime.h>

#define TPB   256
#define ROWS  64         // batch rows per CTA
#define RPT   8          // rows per thread
#define HSTR  66         // floats per unit-row of H: 64 rows + 2 pad (even -> float2 aligned)

typedef unsigned int u32;
typedef unsigned long long ull;

// ---------- packed f32x2 helpers ----------
__device__ __forceinline__ ull pack2(float lo, float hi) {
    ull r; asm("mov.b64 %0, {%1, %2};" : "=l"(r) : "f"(lo), "f"(hi)); return r;
}
__device__ __forceinline__ void unpack2(ull v, float& lo, float& hi) {
    asm("mov.b64 {%0, %1}, %2;" : "=f"(lo), "=f"(hi) : "l"(v));
}
__device__ __forceinline__ ull ffma2(ull a, ull b, ull c) {
    ull d; asm("fma.rn.f32x2 %0, %1, %2, %3;" : "=l"(d) : "l"(a), "l"(b), "l"(c)); return d;
}

// ---------- HW tanh (1 MUFU op, Turing+) ----------
__device__ __forceinline__ float tanh_hw(float x) {
    float y; asm("tanh.approx.f32 %0, %1;" : "=f"(y) : "f"(x)); return y;
}
__device__ __forceinline__ float sigm(float x) {       // sigma(x) = 0.5 + 0.5*tanh(x/2)
    return fmaf(0.5f, tanh_hw(0.5f * x), 0.5f);
}

// SMEM layout (floats):
//   sU [64][256] = 16384 | sH [2][64*HSTR] = 2*4224 | sW[256] sB[256] sWd[64] sX[320]
#define OFF_U   0
#define OFF_H0  16384
#define OFF_H1  (OFF_H0 + 64*HSTR)
#define OFF_W   (OFF_H0 + 2*64*HSTR)
#define OFF_B   (OFF_W + 256)
#define OFF_WD  (OFF_B + 256)
#define OFF_X   (OFF_WD + 64)
#define SMEM_FLOATS (OFF_X + ROWS*5)        // 25728 floats = 102912 B

__global__ void __launch_bounds__(TPB, 2)
lstm_gemm(const float* __restrict__ x, const float* __restrict__ W,
          const float* __restrict__ U, const float* __restrict__ b,
          const float* __restrict__ Wd, const float* __restrict__ bd,
          float* __restrict__ out, int Bn)
{
    extern __shared__ float sm[];
    float* sU  = sm + OFF_U;
    float* sW  = sm + OFF_W;
    float* sB  = sm + OFF_B;
    float* sWd = sm + OFF_WD;
    float* sX  = sm + OFF_X;

    const int tid = threadIdx.x;
    const int cx  = tid & 31;       // column-thread: owns units {cx, cx+32}
    const int ry  = tid >> 5;       // row-thread: owns rows [ry*8, ry*8+8)
    const int r0  = ry * RPT;
    const long rowBase = (long)blockIdx.x * ROWS;

    // ---- stage weights + this CTA's x slice ----
    {
        const float4* Us = (const float4*)U;
        float4* Ud = (float4*)sU;
#pragma unroll
        for (int i = 0; i < 16; ++i) Ud[tid + i * TPB] = Us[tid + i * TPB];
        sW[tid] = W[tid];
        sB[tid] = b[tid];
        if (tid < 64) sWd[tid] = Wd[tid];
        const float* xs = x + rowBase * 5;
        for (int i = tid; i < ROWS * 5; i += TPB)
            if (rowBase * 5 + i < (long)Bn * 5) sX[i] = xs[i];
    }
    __syncthreads();

    const int u0 = cx, u1 = cx + 32;
    const float wd0 = sWd[u0], wd1 = sWd[u1];

    float c[RPT * 2];               // c-state: [row][unit]
#pragma unroll
    for (int i = 0; i < RPT * 2; ++i) c[i] = 0.f;

    float part[RPT];                // dense partials (t==4 only)

#pragma unroll 1
    for (int t = 0; t < 5; ++t) {
        ull acc[32];                // z tile: 4 row-pairs x 8 cols (4 gates x 2 units)
#pragma unroll
        for (int i = 0; i < 32; ++i) acc[i] = 0ull;

        if (t > 0) {
            const float* Hc = sm + (((t - 1) & 1) ? OFF_H1 : OFF_H0);
            const float* Ap = Hc + r0;          // H[k][row], this thread's 8 rows
            const float* Bp = sU + cx;
#pragma unroll 4
            for (int k = 0; k < 64; ++k) {
                ull av[4];                       // 4 row-pairs of h (warp-uniform broadcast)
#pragma unroll
                for (int j = 0; j < 4; ++j) {
                    float2 a2 = *(const float2*)(Ap + k * HSTR + 2 * j);
                    av[j] = pack2(a2.x, a2.y);
                }
                ull bv[8];                       // 8 cols of U, duplicated (stride-1 LDS)
#pragma unroll
                for (int g = 0; g < 4; ++g) {
                    const float b0 = Bp[k * 256 + g * 64];
                    const float b1 = Bp[k * 256 + g * 64 + 32];
                    bv[g * 2 + 0] = pack2(b0, b0);
                    bv[g * 2 + 1] = pack2(b1, b1);
                }
#pragma unroll
                for (int rp = 0; rp < 4; ++rp)
#pragma unroll
                    for (int cs = 0; cs < 8; ++cs)
                        acc[rp * 8 + cs] = ffma2(av[rp], bv[cs], acc[rp * 8 + cs]);
            }
        }

        // ---- epilogue: z = acc + x*W + b, gates, c/h update ----
        float* Hn = sm + ((t & 1) ? OFF_H1 : OFF_H0);
        float wv[8], bvv[8];
#pragma unroll
        for (int g = 0; g < 4; ++g) {
            wv[g * 2]     = sW[g * 64 + u0];  wv[g * 2 + 1]  = sW[g * 64 + u1];
            bvv[g * 2]    = sB[g * 64 + u0];  bvv[g * 2 + 1] = sB[g * 64 + u1];
        }
        const bool last = (t == 4);

#pragma unroll
        for (int rp = 0; rp < 4; ++rp) {
            float z0[8], z1[8];
#pragma unroll
            for (int cs = 0; cs < 8; ++cs) unpack2(acc[rp * 8 + cs], z0[cs], z1[cs]);
#pragma unroll
            for (int h2 = 0; h2 < 2; ++h2) {
                const int r = 2 * rp + h2;
                const float xr = sX[(r0 + r) * 5 + t];
                const float* zz = h2 ? z1 : z0;
#pragma unroll
                for (int uh = 0; uh < 2; ++uh) {
                    const float zi = zz[0 + uh] + fmaf(xr, wv[0 + uh], bvv[0 + uh]);
                    const float zf = zz[2 + uh] + fmaf(xr, wv[2 + uh], bvv[2 + uh]);
                    const float zg = zz[4 + uh] + fmaf(xr, wv[4 + uh], bvv[4 + uh]);
                    const float zo = zz[6 + uh] + fmaf(xr, wv[6 + uh], bvv[6 + uh]);
                    const float ig = sigm(zi), fg = sigm(zf);
                    const float gg = tanh_hw(zg), og = sigm(zo);
                    const float cn = fmaf(fg, c[r * 2 + uh], ig * gg);
                    c[r * 2 + uh] = cn;
                    const float h = og * tanh_hw(cn);
                    if (!last) {
                        Hn[(cx + uh * 32) * HSTR + r0 + r] = h;   // 2-way STS max
                    } else {
                        if (uh == 0) part[r] = h * wd0;
                        else         part[r] = fmaf(h, wd1, part[r]);
                    }
                }
            }
        }

        if (!last) {
            __syncthreads();        // h visible to all warps before next GEMM
        } else {
            // Dense(1, relu): reduce over units = over the 32 cx lanes of this warp
#pragma unroll
            for (int r = 0; r < RPT; ++r) {
#pragma unroll
                for (int s = 16; s; s >>= 1)
                    part[r] += __shfl_xor_sync(0xFFFFFFFFu, part[r], s);
            }
            if (cx == 0) {
                const float bdv = __ldg(bd);
#pragma unroll
                for (int r = 0; r < RPT; ++r) {
                    const long orow = rowBase + r0 + r;
                    if (orow < Bn) out[orow] = fmaxf(part[r] + bdv, 0.f);
                }
            }
        }
    }
}

extern "C" void kernel_launch(void* const* d_in, const int* in_sizes, int n_in,
                              void* d_out, int out_size) {
    const float* x  = (const float*)d_in[0];
    const float* W  = (const float*)d_in[1];
    const float* U  = (const float*)d_in[2];
    const float* b  = (const float*)d_in[3];
    const float* Wd = (const float*)d_in[4];
    const float* bd = (const float*)d_in[5];
    float* out = (float*)d_out;

    const int Bn = in_sizes[0] / 5;                           // x is [B, 5, 1]
    const int smem_bytes = SMEM_FLOATS * (int)sizeof(float);  // 102912 B -> 2 CTAs/SM

    cudaFuncSetAttribute(lstm_gemm, cudaFuncAttributeMaxDynamicSharedMemorySize,
                         smem_bytes);

    const int grid = (Bn + ROWS - 1) / ROWS;
    lstm_gemm<<<grid, TPB, smem_bytes>>>(x, W, U, b, Wd, bd, out, Bn);
}

// round 7
// speedup vs baseline: 2.8439x; 1.0148x over previous
#include <cuda_runtime.h>

#define TPB   256
#define ROWS  64         // batch rows per CTA
#define RPT   8          // rows per thread
#define HSTR  66         // floats per unit-row of H: 64 rows + 2 pad (even -> float2 aligned)

typedef unsigned int u32;
typedef unsigned long long ull;

// ---------- packed f32x2 helpers ----------
__device__ __forceinline__ ull pack2(float lo, float hi) {
    ull r; asm("mov.b64 %0, {%1, %2};" : "=l"(r) : "f"(lo), "f"(hi)); return r;
}
__device__ __forceinline__ void unpack2(ull v, float& lo, float& hi) {
    asm("mov.b64 {%0, %1}, %2;" : "=f"(lo), "=f"(hi) : "l"(v));
}
__device__ __forceinline__ ull ffma2(ull a, ull b, ull c) {
    ull d; asm("fma.rn.f32x2 %0, %1, %2, %3;" : "=l"(d) : "l"(a), "l"(b), "l"(c)); return d;
}

// ---------- HW tanh (1 MUFU op) ----------
__device__ __forceinline__ float tanh_hw(float x) {
    float y; asm("tanh.approx.f32 %0, %1;" : "=f"(y) : "f"(x)); return y;
}
__device__ __forceinline__ float sigm(float x) {       // sigma(x) = 0.5 + 0.5*tanh(x/2)
    return fmaf(0.5f, tanh_hw(0.5f * x), 0.5f);
}

// SMEM layout (floats):
//   sU [64][256] = 16384 | sH [2][64*HSTR] = 2*4224 | sW[256] sB[256] sWd[64] sX[320]
#define OFF_U   0
#define OFF_H0  16384
#define OFF_H1  (OFF_H0 + 64*HSTR)
#define OFF_W   (OFF_H0 + 2*64*HSTR)
#define OFF_B   (OFF_W + 256)
#define OFF_WD  (OFF_B + 256)
#define OFF_X   (OFF_WD + 64)
#define SMEM_FLOATS (OFF_X + ROWS*5)        // 25728 floats = 102912 B

__global__ void __launch_bounds__(TPB, 2)
lstm_gemm(const float* __restrict__ x, const float* __restrict__ W,
          const float* __restrict__ U, const float* __restrict__ b,
          const float* __restrict__ Wd, const float* __restrict__ bd,
          float* __restrict__ out, int Bn)
{
    extern __shared__ float sm[];
    float* sU  = sm + OFF_U;
    float* sW  = sm + OFF_W;
    float* sB  = sm + OFF_B;
    float* sWd = sm + OFF_WD;
    float* sX  = sm + OFF_X;

    const int tid = threadIdx.x;
    const int cx  = tid & 31;       // column-thread: owns units {cx, cx+32}
    const int ry  = tid >> 5;       // row-thread (warp id): owns rows [ry*8, ry*8+8)
    const int r0  = ry * RPT;
    const long rowBase = (long)blockIdx.x * ROWS;

    // ---- stage weights + this CTA's x slice ----
    {
        const float4* Us = (const float4*)U;
        float4* Ud = (float4*)sU;
#pragma unroll
        for (int i = 0; i < 16; ++i) Ud[tid + i * TPB] = Us[tid + i * TPB];
        sW[tid] = W[tid];
        sB[tid] = b[tid];
        if (tid < 64) sWd[tid] = Wd[tid];
        const float* xs = x + rowBase * 5;
        for (int i = tid; i < ROWS * 5; i += TPB)
            if (rowBase * 5 + i < (long)Bn * 5) sX[i] = xs[i];
    }
    __syncthreads();     // staging is cross-warp: keep this one barrier

    const int u0 = cx, u1 = cx + 32;
    const float wd0 = sWd[u0], wd1 = sWd[u1];

    float c[RPT * 2];               // c-state: [row][unit]
#pragma unroll
    for (int i = 0; i < RPT * 2; ++i) c[i] = 0.f;

    float part[RPT];                // dense partials (t==4 only)

#pragma unroll 1
    for (int t = 0; t < 5; ++t) {
        ull acc[32];                // z tile: 4 row-pairs x 8 cols (4 gates x 2 units)
#pragma unroll
        for (int i = 0; i < 32; ++i) acc[i] = 0ull;

        if (t > 0) {
            const float* Hc = sm + (((t - 1) & 1) ? OFF_H1 : OFF_H0);
            const float* Ap = Hc + r0;          // H[k][row], this warp's 8 rows
            const float* Bp = sU + cx;
#pragma unroll 4
            for (int k = 0; k < 64; ++k) {
                ull av[4];                       // 4 row-pairs of h (warp-uniform broadcast)
#pragma unroll
                for (int j = 0; j < 4; ++j) {
                    float2 a2 = *(const float2*)(Ap + k * HSTR + 2 * j);
                    av[j] = pack2(a2.x, a2.y);
                }
                ull bv[8];                       // 8 cols of U, duplicated (stride-1 LDS)
#pragma unroll
                for (int g = 0; g < 4; ++g) {
                    const float b0 = Bp[k * 256 + g * 64];
                    const float b1 = Bp[k * 256 + g * 64 + 32];
                    bv[g * 2 + 0] = pack2(b0, b0);
                    bv[g * 2 + 1] = pack2(b1, b1);
                }
#pragma unroll
                for (int rp = 0; rp < 4; ++rp)
#pragma unroll
                    for (int cs = 0; cs < 8; ++cs)
                        acc[rp * 8 + cs] = ffma2(av[rp], bv[cs], acc[rp * 8 + cs]);
            }
        }

        // ---- epilogue: z = acc + x*W + b, gates, c/h update ----
        float* Hn = sm + ((t & 1) ? OFF_H1 : OFF_H0);
        float wv[8], bvv[8];
#pragma unroll
        for (int g = 0; g < 4; ++g) {
            wv[g * 2]     = sW[g * 64 + u0];  wv[g * 2 + 1]  = sW[g * 64 + u1];
            bvv[g * 2]    = sB[g * 64 + u0];  bvv[g * 2 + 1] = sB[g * 64 + u1];
        }
        const bool last = (t == 4);

#pragma unroll
        for (int rp = 0; rp < 4; ++rp) {
            float z0[8], z1[8];
#pragma unroll
            for (int cs = 0; cs < 8; ++cs) unpack2(acc[rp * 8 + cs], z0[cs], z1[cs]);
#pragma unroll
            for (int h2 = 0; h2 < 2; ++h2) {
                const int r = 2 * rp + h2;
                const float xr = sX[(r0 + r) * 5 + t];
                const float* zz = h2 ? z1 : z0;
#pragma unroll
                for (int uh = 0; uh < 2; ++uh) {
                    const float zi = zz[0 + uh] + fmaf(xr, wv[0 + uh], bvv[0 + uh]);
                    const float zf = zz[2 + uh] + fmaf(xr, wv[2 + uh], bvv[2 + uh]);
                    const float zg = zz[4 + uh] + fmaf(xr, wv[4 + uh], bvv[4 + uh]);
                    const float zo = zz[6 + uh] + fmaf(xr, wv[6 + uh], bvv[6 + uh]);
                    const float ig = sigm(zi), fg = sigm(zf);
                    const float gg = tanh_hw(zg), og = sigm(zo);
                    const float cn = fmaf(fg, c[r * 2 + uh], ig * gg);
                    c[r * 2 + uh] = cn;
                    const float h = og * tanh_hw(cn);
                    if (!last) {
                        Hn[(cx + uh * 32) * HSTR + r0 + r] = h;   // 2-way STS max
                    } else {
                        if (uh == 0) part[r] = h * wd0;
                        else         part[r] = fmaf(h, wd1, part[r]);
                    }
                }
            }
        }

        if (!last) {
            // H rows are warp-private: producer lanes and consumer lanes are in
            // THIS warp only -> warp-level sync suffices (no CTA barrier).
            __syncwarp(0xFFFFFFFFu);
        } else {
            // Dense(1, relu): reduce over units = over the 32 cx lanes of this warp
#pragma unroll
            for (int r = 0; r < RPT; ++r) {
#pragma unroll
                for (int s = 16; s; s >>= 1)
                    part[r] += __shfl_xor_sync(0xFFFFFFFFu, part[r], s);
            }
            if (cx == 0) {
                const float bdv = __ldg(bd);
#pragma unroll
                for (int r = 0; r < RPT; ++r) {
                    const long orow = rowBase + r0 + r;
                    if (orow < Bn) out[orow] = fmaxf(part[r] + bdv, 0.f);
                }
            }
        }
    }
}

extern "C" void kernel_launch(void* const* d_in, const int* in_sizes, int n_in,
                              void* d_out, int out_size) {
    const float* x  = (const float*)d_in[0];
    const float* W  = (const float*)d_in[1];
    const float* U  = (const float*)d_in[2];
    const float* b  = (const float*)d_in[3];
    const float* Wd = (const float*)d_in[4];
    const float* bd = (const float*)d_in[5];
    float* out = (float*)d_out;

    const int Bn = in_sizes[0] / 5;                           // x is [B, 5, 1]
    const int smem_bytes = SMEM_FLOATS * (int)sizeof(float);  // 102912 B -> 2 CTAs/SM

    cudaFuncSetAttribute(lstm_gemm, cudaFuncAttributeMaxDynamicSharedMemorySize,
                         smem_bytes);

    const int grid = (Bn + ROWS - 1) / ROWS;
    lstm_gemm<<<grid, TPB, smem_bytes>>>(x, W, U, b, Wd, bd, out, Bn);
}